// round 16
// baseline (speedup 1.0000x reference)
#include <cuda_runtime.h>
#include <cuda_fp16.h>
#include <cstdint>

// ---------------------------------------------------------------------------
// Block-diagonal linear (256x0e+256x1o+256x2e): 3 GEMMs over rows (z,i):
//   A'[z*D+i][u] = feat[z, XOFF + u*D + i];  C = A' * W_b / 16.
// R16 = R15 (fp16 m16n8k16, RN-fp16 pre-fragmented B, cp.async native fp32 A,
// 3-stage ring, 1 barrier/chunk) with 256-thread CTAs / 8 warps, warp tile
// 32x64 (P=4,Q=2): 4 warps per SMSP for latency hiding (occ 12->24%),
// ~105 regs, A-replication stays at 2.
// ---------------------------------------------------------------------------
#define HX_BZ   50000
#define HX_FEAT 2304

static constexpr int NTH = 256;   // 8 warps: wm = wid>>1 (4x32 rows), wn = wid&1

// pre-fragmented fp16 weights: [b*2+nh][ch(8)][512 uint4] = 24576 uint4
__device__ uint4 g_wfrag[24576];

// ---------------------------------------------------------------------------
__device__ __forceinline__ uint32_t pack2(float lo, float hi) {
    __half2 h = __floats2half2_rn(lo, hi);   // low half = lower k
    return *(uint32_t*)&h;
}

__device__ __forceinline__ void mma16(float* c, const uint32_t* a,
                                      uint32_t b0, uint32_t b1) {
    asm volatile(
        "mma.sync.aligned.m16n8k16.row.col.f32.f16.f16.f32 "
        "{%0,%1,%2,%3}, {%4,%5,%6,%7}, {%8,%9}, {%0,%1,%2,%3};"
        : "+f"(c[0]), "+f"(c[1]), "+f"(c[2]), "+f"(c[3])
        : "r"(a[0]), "r"(a[1]), "r"(a[2]), "r"(a[3]), "r"(b0), "r"(b1));
}

#define CP_A16(dst, src, sz)                                               \
    asm volatile("cp.async.cg.shared.global [%0], [%1], 16, %2;"           \
                 :: "r"(dst), "l"(src), "r"(sz) : "memory")
#define CP_COMMIT() asm volatile("cp.async.commit_group;" ::: "memory")
#define CP_WAIT(n)  asm volatile("cp.async.wait_group %0;" :: "n"(n) : "memory")

__device__ __forceinline__ uint32_t smem_u32(const void* p) {
    uint32_t a;
    asm("{ .reg .u64 t; cvta.to.shared.u64 t, %1; cvt.u32.u64 %0, t; }"
        : "=r"(a) : "l"(p));
    return a;
}

// ---------------------------------------------------------------------------
// Prepass: RN-fp16 + fragment-order all weights (once, ~3us). Layout is
// identical to R15 (wn in {0,1}, nfp in 0..3, s in {0,1}).
__global__ void prep_w(const float* __restrict__ wt) {
    const int t = blockIdx.x * blockDim.x + threadIdx.x;
    if (t >= 24576) return;
    const int e  = t & 511;
    const int ch = (t >> 9) & 7;
    const int bn = t >> 12;              // b*2 + nh
    const int b  = bn >> 1, nh = bn & 1;
    const int woff = (b == 0) ? 0 : (b == 1) ? 65536 : 131072;
    const int lane = e & 31, g = lane >> 2, tg = lane & 3;
    const int idx = e >> 5;              // 0..15
    const int nfp = idx & 3, wn = (idx >> 2) & 1, s = idx >> 3;
    const int k0 = 32 * ch + 16 * s + 2 * tg;
    const int n  = 128 * nh + 64 * wn + 16 * nfp + g;
    const float* wp = wt + woff;
    uint4 q;
    q.x = pack2(wp[k0 * 256 + n],           wp[(k0 + 1) * 256 + n]);
    q.y = pack2(wp[(k0 + 8) * 256 + n],     wp[(k0 + 9) * 256 + n]);
    q.z = pack2(wp[k0 * 256 + n + 8],       wp[(k0 + 1) * 256 + n + 8]);
    q.w = pack2(wp[(k0 + 8) * 256 + n + 8], wp[(k0 + 9) * 256 + n + 8]);
    g_wfrag[t] = q;
}

// ---------------------------------------------------------------------------
template<int D, int XOFF, int MTOT>
__global__ void __launch_bounds__(NTH, 2)
lin_k(const float* __restrict__ feat, float* __restrict__ out)
{
    constexpr int SD   = (D == 1) ? 40 : (D == 3) ? 104 : 168;
    constexpr int NZ   = (D == 1) ? 128 : (D == 3) ? 44 : 27;
    constexpr int F4Z  = 8 * D;
    constexpr int TOT4 = NZ * F4Z;
    constexpr int PA   = (TOT4 + NTH - 1) / NTH;       // 4 / 5 / 5
    constexpr int ABUF = NZ * SD * 4;
    constexpr int BOFF = 3 * ABUF;
    constexpr int BBUF = 8192;                         // fp16 B chunk

    extern __shared__ char smem[];
    const uint32_t smb = smem_u32(smem);

    const int tid  = threadIdx.x;
    const int lane = tid & 31;
    const int wid  = tid >> 5;
    const int g    = lane >> 2;
    const int tg   = lane & 3;
    const int wm   = wid >> 1;     // 4 x 32 rows
    const int wn   = wid & 1;      // 2 x 64 cols

    const int bid  = blockIdx.x;
    const int tile = bid >> 1;
    const int nh   = bid & 1;
    const int m0   = tile * 128;
    const int z0   = m0 / D;

    const int bsel = ((D == 1) ? 0 : (D == 3) ? 2 : 4) + nh;
    const char* bbase = (const char*)(g_wfrag + bsel * 4096);

    // ---- A staging decode (compact) ----
    uint32_t a_soff[PA];     // 0xFFFFFFFF -> skip
    uint32_t a_goff[PA];     // 0xFFFFFFFF -> zero-fill
    #pragma unroll
    for (int p = 0; p < PA; p++) {
        const int e  = tid + NTH * p;
        const int zr = e / F4Z;
        const int q  = e - zr * F4Z;
        const int z  = z0 + zr;
        a_soff[p] = (e < TOT4) ? (uint32_t)(zr * SD * 4 + q * 16) : 0xFFFFFFFFu;
        a_goff[p] = (e < TOT4 && z < HX_BZ)
                  ? (uint32_t)((z * HX_FEAT + XOFF + q * 4) * 4) : 0xFFFFFFFFu;
    }

    auto issue = [&](int ch, int st) {
        const uint32_t sa0 = smb + st * ABUF;
        const uint32_t aoff = (uint32_t)(ch * (32 * D) * 4);
        #pragma unroll
        for (int p = 0; p < PA; p++) {
            if (a_soff[p] != 0xFFFFFFFFu) {
                const bool ok = (a_goff[p] != 0xFFFFFFFFu);
                const char* src = (const char*)feat + (ok ? a_goff[p] + aoff : 0u);
                CP_A16(sa0 + a_soff[p], src, ok ? 16u : 0u);
            }
        }
        const uint32_t sb0 = smb + BOFF + st * BBUF + tid * 16;
        const char* bsrc = bbase + ch * BBUF + tid * 16;
        #pragma unroll
        for (int p = 0; p < 2; p++)
            CP_A16(sb0 + p * (NTH * 16), bsrc + p * (NTH * 16), 16u);
        CP_COMMIT();
    };

    // ---- fragment row decode for A (once per tile) ----
    int arow[2][2];
    #pragma unroll
    for (int mf = 0; mf < 2; mf++)
        #pragma unroll
        for (int hh = 0; hh < 2; hh++) {
            const int r  = wm * 32 + mf * 16 + hh * 8 + g;
            const int gr = m0 + r;
            const int z  = gr / D;
            const int i  = gr - z * D;
            arow[mf][hh] = (z - z0) * SD + i;
        }

    // ---- accumulators: 2 m-frags x 8 n-frags ----
    float c[2][8][4];
    #pragma unroll
    for (int mf = 0; mf < 2; mf++)
        #pragma unroll
        for (int nf = 0; nf < 8; nf++)
            #pragma unroll
            for (int q = 0; q < 4; q++) c[mf][nf][q] = 0.0f;

    auto compute = [&](int st) {
        const float* Af = (const float*)(smem + st * ABUF);
        const uint4* Bs = (const uint4*)(smem + BOFF + st * BBUF);
        #pragma unroll
        for (int s = 0; s < 2; s++) {            // two k16 steps per chunk
            uint32_t a[2][4];
            #pragma unroll
            for (int mf = 0; mf < 2; mf++) {
                if (D == 1) {
                    const int kb = 16 * s + 2 * tg;
                    const float2 p00 = *(const float2*)&Af[arow[mf][0] + kb];
                    const float2 p10 = *(const float2*)&Af[arow[mf][1] + kb];
                    const float2 p01 = *(const float2*)&Af[arow[mf][0] + kb + 8];
                    const float2 p11 = *(const float2*)&Af[arow[mf][1] + kb + 8];
                    a[mf][0] = pack2(p00.x, p00.y);
                    a[mf][1] = pack2(p10.x, p10.y);
                    a[mf][2] = pack2(p01.x, p01.y);
                    a[mf][3] = pack2(p11.x, p11.y);
                } else {
                    const int kb = (16 * s + 2 * tg) * D;
                    const int r0 = arow[mf][0], r1 = arow[mf][1];
                    a[mf][0] = pack2(Af[r0 + kb],         Af[r0 + kb + D]);
                    a[mf][1] = pack2(Af[r1 + kb],         Af[r1 + kb + D]);
                    a[mf][2] = pack2(Af[r0 + kb + 8 * D], Af[r0 + kb + 9 * D]);
                    a[mf][3] = pack2(Af[r1 + kb + 8 * D], Af[r1 + kb + 9 * D]);
                }
            }
            #pragma unroll
            for (int nfp = 0; nfp < 4; nfp++) {
                const uint4 b = Bs[((s * 2 + wn) * 4 + nfp) * 32 + lane];
                #pragma unroll
                for (int mf = 0; mf < 2; mf++) {
                    mma16(c[mf][2 * nfp],     a[mf], b.x, b.y);
                    mma16(c[mf][2 * nfp + 1], a[mf], b.z, b.w);
                }
            }
        }
    };

    // ---- pipeline: joint 3-stage ring, depth-2 prefetch, 1 barrier/chunk --
    issue(0, 0);
    issue(1, 1);
    CP_WAIT(1);
    __syncthreads();

    #pragma unroll 1
    for (int ch = 0; ch < 8; ch++) {
        compute(ch % 3);
        if (ch < 7) {
            if (ch + 2 < 8) {
                issue(ch + 2, (ch + 2) % 3);
                CP_WAIT(1);
            } else {
                CP_WAIT(0);
            }
            __syncthreads();
        }
    }

    // ---- epilogue: direct scatter, scale 1/sqrt(256) ----
    const float S = 0.0625f;
    #pragma unroll
    for (int mf = 0; mf < 2; mf++) {
        #pragma unroll
        for (int rr = 0; rr < 2; rr++) {
            const int gr = m0 + wm * 32 + mf * 16 + rr * 8 + g;
            if (gr < MTOT) {
                const int z = gr / D;
                const int i = gr - z * D;
                float* op = out + (size_t)z * HX_FEAT + XOFF + i
                          + (size_t)(nh * 128) * D;
                #pragma unroll
                for (int nf = 0; nf < 8; nf++) {
                    const int n = wn * 64 + (nf >> 1) * 16 + (nf & 1) * 8 + 2 * tg;
                    if (D == 1) {
                        float2 v;
                        v.x = c[mf][nf][rr * 2 + 0] * S;
                        v.y = c[mf][nf][rr * 2 + 1] * S;
                        *(float2*)(op + n) = v;
                    } else {
                        op[(size_t)n * D]       = c[mf][nf][rr * 2 + 0] * S;
                        op[(size_t)(n + 1) * D] = c[mf][nf][rr * 2 + 1] * S;
                    }
                }
            }
        }
    }
}

// ---------------------------------------------------------------------------
extern "C" void kernel_launch(void* const* d_in, const int* in_sizes, int n_in,
                              void* d_out, int out_size) {
    const float* feat = (const float*)d_in[0];
    const float* wt   = (const float*)d_in[1];
    float* out        = (float*)d_out;

    constexpr int SM1 = 3 * (128 * 40 * 4) + 3 * 8192;   // 86016
    constexpr int SM3 = 3 * (44 * 104 * 4) + 3 * 8192;   // 79488
    constexpr int SM5 = 3 * (27 * 168 * 4) + 3 * 8192;   // 78912

    auto k1 = lin_k<1, 0,    50000>;
    auto k3 = lin_k<3, 256,  150000>;
    auto k5 = lin_k<5, 1024, 250000>;

    cudaFuncSetAttribute(k1, cudaFuncAttributeMaxDynamicSharedMemorySize, SM1);
    cudaFuncSetAttribute(k3, cudaFuncAttributeMaxDynamicSharedMemorySize, SM3);
    cudaFuncSetAttribute(k5, cudaFuncAttributeMaxDynamicSharedMemorySize, SM5);

    prep_w<<<96, 256>>>(wt);
    k1<<<391 * 2,  NTH, SM1>>>(feat, out);
    k3<<<1172 * 2, NTH, SM3>>>(feat, out);
    k5<<<1954 * 2, NTH, SM5>>>(feat, out);
}

// round 17
// speedup vs baseline: 1.1171x; 1.1171x over previous
#include <cuda_runtime.h>
#include <cuda_fp16.h>
#include <cstdint>

// ---------------------------------------------------------------------------
// Block-diagonal linear (256x0e+256x1o+256x2e): 3 GEMMs over rows (z,i):
//   A'[z*D+i][u] = feat[z, XOFF + u*D + i];  C = A' * W_b / 16.
// R17 = R15 (fp16 m16n8k16, RN-fp16 pre-fragmented B, cp.async native fp32 A,
// 128-thr CTAs / 4 warps / warp tile 64x64, 2 CTAs/SM) with KC=64:
// 4 k-chunks instead of 8 -> half the pipeline seams, 2x compute runs,
// 2-stage ring. A-staging decode on the fly (constant-div), regs stay ~240.
// ---------------------------------------------------------------------------
#define HX_BZ   50000
#define HX_FEAT 2304

static constexpr int NTH = 128;   // 4 warps: wm = wid&1 (2x64 rows), wn = wid>>1

// pre-fragmented fp16 weights: [b*2+nh][ch(4)][1024 uint4] = 24576 uint4
__device__ uint4 g_wfrag[24576];

// ---------------------------------------------------------------------------
__device__ __forceinline__ uint32_t pack2(float lo, float hi) {
    __half2 h = __floats2half2_rn(lo, hi);   // low half = lower k
    return *(uint32_t*)&h;
}

__device__ __forceinline__ void mma16(float* c, const uint32_t* a,
                                      uint32_t b0, uint32_t b1) {
    asm volatile(
        "mma.sync.aligned.m16n8k16.row.col.f32.f16.f16.f32 "
        "{%0,%1,%2,%3}, {%4,%5,%6,%7}, {%8,%9}, {%0,%1,%2,%3};"
        : "+f"(c[0]), "+f"(c[1]), "+f"(c[2]), "+f"(c[3])
        : "r"(a[0]), "r"(a[1]), "r"(a[2]), "r"(a[3]), "r"(b0), "r"(b1));
}

#define CP_A16(dst, src, sz)                                               \
    asm volatile("cp.async.cg.shared.global [%0], [%1], 16, %2;"           \
                 :: "r"(dst), "l"(src), "r"(sz) : "memory")
#define CP_COMMIT() asm volatile("cp.async.commit_group;" ::: "memory")
#define CP_WAIT(n)  asm volatile("cp.async.wait_group %0;" :: "n"(n) : "memory")

__device__ __forceinline__ uint32_t smem_u32(const void* p) {
    uint32_t a;
    asm("{ .reg .u64 t; cvta.to.shared.u64 t, %1; cvt.u32.u64 %0, t; }"
        : "=r"(a) : "l"(p));
    return a;
}

// ---------------------------------------------------------------------------
// Prepass: RN-fp16 + fragment-order all weights (once, ~3us).
// t = bn*4096 + ch*1024 + e;  e = ((s*2+wn)*4+nfp)*32 + lane, s in 0..3
__global__ void prep_w(const float* __restrict__ wt) {
    const int t = blockIdx.x * blockDim.x + threadIdx.x;
    if (t >= 24576) return;
    const int e  = t & 1023;
    const int ch = (t >> 10) & 3;
    const int bn = t >> 12;              // b*2 + nh
    const int b  = bn >> 1, nh = bn & 1;
    const int woff = (b == 0) ? 0 : (b == 1) ? 65536 : 131072;
    const int lane = e & 31, g = lane >> 2, tg = lane & 3;
    const int idx = e >> 5;              // 0..31
    const int nfp = idx & 3, wn = (idx >> 2) & 1, s = idx >> 3;   // s 0..3
    const int k0 = 64 * ch + 16 * s + 2 * tg;
    const int n  = 128 * nh + 64 * wn + 16 * nfp + g;
    const float* wp = wt + woff;
    uint4 q;
    q.x = pack2(wp[k0 * 256 + n],           wp[(k0 + 1) * 256 + n]);
    q.y = pack2(wp[(k0 + 8) * 256 + n],     wp[(k0 + 9) * 256 + n]);
    q.z = pack2(wp[k0 * 256 + n + 8],       wp[(k0 + 1) * 256 + n + 8]);
    q.w = pack2(wp[(k0 + 8) * 256 + n + 8], wp[(k0 + 9) * 256 + n + 8]);
    g_wfrag[t] = q;
}

// ---------------------------------------------------------------------------
template<int D, int XOFF, int MTOT>
__global__ void __launch_bounds__(NTH, 2)
lin_k(const float* __restrict__ feat, float* __restrict__ out)
{
    // A native fp32 layout: per z row, stride SD floats (mod 32 == 8 padding)
    constexpr int SD   = (D == 1) ? 72 : (D == 3) ? 200 : 328;
    constexpr int NZ   = (D == 1) ? 128 : (D == 3) ? 44 : 27;
    constexpr int F4Z  = 16 * D;                       // float4 per z per chunk
    constexpr int TOT4 = NZ * F4Z;                     // 2048 / 2112 / 2160
    constexpr int PA   = (TOT4 + NTH - 1) / NTH;       // 16 / 17 / 17
    constexpr int ABUF = NZ * SD * 4;
    constexpr int BOFF = 2 * ABUF;
    constexpr int BBUF = 16384;                        // fp16 B, K=64 chunk

    extern __shared__ char smem[];
    const uint32_t smb = smem_u32(smem);

    const int tid  = threadIdx.x;
    const int lane = tid & 31;
    const int wid  = tid >> 5;
    const int g    = lane >> 2;
    const int tg   = lane & 3;
    const int wm   = wid & 1;      // 2 x 64 rows
    const int wn   = wid >> 1;     // 2 x 64 cols

    const int bid  = blockIdx.x;
    const int tile = bid >> 1;
    const int nh   = bid & 1;
    const int m0   = tile * 128;
    const int z0   = m0 / D;

    const int bsel = ((D == 1) ? 0 : (D == 3) ? 2 : 4) + nh;
    const char* bbase = (const char*)(g_wfrag + bsel * 4096);

    // ---- staging: decode on the fly (PA too large for precomputed arrays) --
    auto issue = [&](int ch, int st) {
        const uint32_t sa0 = smb + st * ABUF;
        #pragma unroll
        for (int p = 0; p < PA; p++) {
            const int e = tid + NTH * p;
            if (e < TOT4) {
                const int zr = e / F4Z;              // constant divisor
                const int q  = e - zr * F4Z;
                const int z  = z0 + zr;
                const bool ok = (z < HX_BZ);
                const uint32_t dst = sa0 + (uint32_t)(zr * SD + q * 4) * 4;
                const char* src = (const char*)
                    (feat + ((size_t)z * HX_FEAT + XOFF + ch * (64 * D) + q * 4));
                CP_A16(dst, ok ? src : (const char*)feat, ok ? 16u : 0u);
            }
        }
        const uint32_t sb0 = smb + BOFF + st * BBUF + tid * 16;
        const char* bsrc = bbase + ch * BBUF + tid * 16;
        #pragma unroll
        for (int p = 0; p < 8; p++)
            CP_A16(sb0 + p * (NTH * 16), bsrc + p * (NTH * 16), 16u);
        CP_COMMIT();
    };

    // ---- fragment row decode for A (once per tile) ----
    int arow[4][2];
    #pragma unroll
    for (int mf = 0; mf < 4; mf++)
        #pragma unroll
        for (int hh = 0; hh < 2; hh++) {
            const int r  = wm * 64 + mf * 16 + hh * 8 + g;
            const int gr = m0 + r;
            const int z  = gr / D;
            const int i  = gr - z * D;
            arow[mf][hh] = (z - z0) * SD + i;
        }

    // ---- accumulators: 4 m-frags x 8 n-frags ----
    float c[4][8][4];
    #pragma unroll
    for (int mf = 0; mf < 4; mf++)
        #pragma unroll
        for (int nf = 0; nf < 8; nf++)
            #pragma unroll
            for (int q = 0; q < 4; q++) c[mf][nf][q] = 0.0f;

    auto compute = [&](int st) {
        const float* Af = (const float*)(smem + st * ABUF);
        const uint4* Bs = (const uint4*)(smem + BOFF + st * BBUF);
        #pragma unroll
        for (int s = 0; s < 4; s++) {            // four k16 steps per chunk
            uint32_t a[4][4];
            #pragma unroll
            for (int mf = 0; mf < 4; mf++) {
                if (D == 1) {
                    const int kb = 16 * s + 2 * tg;
                    const float2 p00 = *(const float2*)&Af[arow[mf][0] + kb];
                    const float2 p10 = *(const float2*)&Af[arow[mf][1] + kb];
                    const float2 p01 = *(const float2*)&Af[arow[mf][0] + kb + 8];
                    const float2 p11 = *(const float2*)&Af[arow[mf][1] + kb + 8];
                    a[mf][0] = pack2(p00.x, p00.y);
                    a[mf][1] = pack2(p10.x, p10.y);
                    a[mf][2] = pack2(p01.x, p01.y);
                    a[mf][3] = pack2(p11.x, p11.y);
                } else {
                    const int kb = (16 * s + 2 * tg) * D;
                    const int r0 = arow[mf][0], r1 = arow[mf][1];
                    a[mf][0] = pack2(Af[r0 + kb],         Af[r0 + kb + D]);
                    a[mf][1] = pack2(Af[r1 + kb],         Af[r1 + kb + D]);
                    a[mf][2] = pack2(Af[r0 + kb + 8 * D], Af[r0 + kb + 9 * D]);
                    a[mf][3] = pack2(Af[r1 + kb + 8 * D], Af[r1 + kb + 9 * D]);
                }
            }
            #pragma unroll
            for (int nfp = 0; nfp < 4; nfp++) {
                const uint4 b = Bs[((s * 2 + wn) * 4 + nfp) * 32 + lane];
                #pragma unroll
                for (int mf = 0; mf < 4; mf++) {
                    mma16(c[mf][2 * nfp],     a[mf], b.x, b.y);
                    mma16(c[mf][2 * nfp + 1], a[mf], b.z, b.w);
                }
            }
        }
    };

    // ---- pipeline: 2-stage ring over 4 chunks ----
    issue(0, 0);
    issue(1, 1);
    CP_WAIT(1);
    __syncthreads();

    #pragma unroll 1
    for (int ch = 0; ch < 4; ch++) {
        compute(ch & 1);
        if (ch < 3) {
            __syncthreads();                 // all warps done reading buf ch&1
            if (ch + 2 < 4) {
                issue(ch + 2, ch & 1);       // rewrite the freed buffer
                CP_WAIT(1);                  // chunk ch+1 landed
            } else {
                CP_WAIT(0);                  // last chunk landed
            }
            __syncthreads();                 // cross-thread visibility
        }
    }

    // ---- epilogue: direct scatter, scale 1/sqrt(256) ----
    const float S = 0.0625f;
    #pragma unroll
    for (int mf = 0; mf < 4; mf++) {
        #pragma unroll
        for (int rr = 0; rr < 2; rr++) {
            const int gr = m0 + wm * 64 + mf * 16 + rr * 8 + g;
            if (gr < MTOT) {
                const int z = gr / D;
                const int i = gr - z * D;
                float* op = out + (size_t)z * HX_FEAT + XOFF + i
                          + (size_t)(nh * 128) * D;
                #pragma unroll
                for (int nf = 0; nf < 8; nf++) {
                    const int n = wn * 64 + (nf >> 1) * 16 + (nf & 1) * 8 + 2 * tg;
                    if (D == 1) {
                        float2 v;
                        v.x = c[mf][nf][rr * 2 + 0] * S;
                        v.y = c[mf][nf][rr * 2 + 1] * S;
                        *(float2*)(op + n) = v;
                    } else {
                        op[(size_t)n * D]       = c[mf][nf][rr * 2 + 0] * S;
                        op[(size_t)(n + 1) * D] = c[mf][nf][rr * 2 + 1] * S;
                    }
                }
            }
        }
    }
}

// ---------------------------------------------------------------------------
extern "C" void kernel_launch(void* const* d_in, const int* in_sizes, int n_in,
                              void* d_out, int out_size) {
    const float* feat = (const float*)d_in[0];
    const float* wt   = (const float*)d_in[1];
    float* out        = (float*)d_out;

    // smem = 2 A stages + 2 B stages
    constexpr int SM1 = 2 * (128 * 72 * 4)  + 2 * 16384;   // 106496
    constexpr int SM3 = 2 * (44 * 200 * 4)  + 2 * 16384;   // 103168
    constexpr int SM5 = 2 * (27 * 328 * 4)  + 2 * 16384;   // 103616

    auto k1 = lin_k<1, 0,    50000>;
    auto k3 = lin_k<3, 256,  150000>;
    auto k5 = lin_k<5, 1024, 250000>;

    cudaFuncSetAttribute(k1, cudaFuncAttributeMaxDynamicSharedMemorySize, SM1);
    cudaFuncSetAttribute(k3, cudaFuncAttributeMaxDynamicSharedMemorySize, SM3);
    cudaFuncSetAttribute(k5, cudaFuncAttributeMaxDynamicSharedMemorySize, SM5);

    prep_w<<<96, 256>>>(wt);
    k1<<<391 * 2,  NTH, SM1>>>(feat, out);
    k3<<<1172 * 2, NTH, SM3>>>(feat, out);
    k5<<<1954 * 2, NTH, SM5>>>(feat, out);
}